// round 11
// baseline (speedup 1.0000x reference)
#include <cuda_runtime.h>
#include <cstdint>

#define N_SLOTS 524288
#define DIM     128
#define NF      138        // DIM_MEM + 1 + 1 + 7 + 1
#define DIN     1024
#define TILE    128
#define HALO    3
#define TPB     512
#define NWARPS  16
#define RPW     8                  // rows per warp
#define NTILES  (N_SLOTS / TILE)   // 4096
#define MB      152                // 1 CTA per SM, all resident
#define FB      80                 // factor-stage blocks (<=MB -> wave-1 resident)
#define KCH     16                 // k chunks of 64 rows
#define NBUF    3
#define BUF_BYTES (TILE * DIM * 4) // 65536

// dynamic smem layout (bytes)
#define OFF_BUF  0
#define OFF_E    (NBUF * BUF_BYTES)                 // 196608
#define OFF_RED  (OFF_E + NBUF * 136 * 4)           // 198240
#define OFF_F    (OFF_RED + NWARPS * DIM * 4)       // 206432
#define OFF_P    (OFF_F + 144 * 4)                  // 207008
#define OFF_ZW   (OFF_P + 12 * 4)                   // 207056
#define OFF_MBAR (OFF_ZW + NWARPS * 4)              // 207120
#define OFF_LAST (OFF_MBAR + NBUF * 8)              // 207144
#define SMEM_TOTAL (OFF_LAST + 16)                  // 207160

// scratch (allocation-free: __device__ globals)
__device__ __align__(16) float g_fpart[KCH][160];
__device__ float g_UpartT[DIM][MB];
__device__ float g_Zpart[MB];
__device__ int   g_cnt1 = 0;
__device__ int   g_cnt2 = 0;

#define FULLM 0xffffffffu

__device__ __forceinline__ uint32_t smem_u32(const void* p) {
    return (uint32_t)__cvta_generic_to_shared(p);
}
__device__ __forceinline__ void mbar_init(uint32_t a, uint32_t cnt) {
    asm volatile("mbarrier.init.shared.b64 [%0], %1;" :: "r"(a), "r"(cnt) : "memory");
}
__device__ __forceinline__ void mbar_expect_tx(uint32_t a, uint32_t bytes) {
    asm volatile("mbarrier.arrive.expect_tx.shared.b64 _, [%0], %1;" :: "r"(a), "r"(bytes) : "memory");
}
__device__ __forceinline__ void tma_bulk_g2s(uint32_t dst, const void* src, uint32_t bytes, uint32_t mbar) {
    asm volatile("cp.async.bulk.shared::cta.global.mbarrier::complete_tx::bytes [%0], [%1], %2, [%3];"
                 :: "r"(dst), "l"(src), "r"(bytes), "r"(mbar) : "memory");
}
__device__ __forceinline__ void mbar_wait(uint32_t a, uint32_t parity) {
    asm volatile("{\n\t.reg .pred P;\n\tWL%=:\n\t"
                 "mbarrier.try_wait.parity.acquire.cta.shared::cta.b64 P, [%0], %1;\n\t"
                 "@!P bra WL%=;\n\t}" :: "r"(a), "r"(parity) : "memory");
}
__device__ __forceinline__ void rowstat(const float4 m, const float4 kv, float& d, float& q) {
    d = m.x*kv.x + m.y*kv.y + m.z*kv.z + m.w*kv.w;
    q = m.x*m.x + m.y*m.y + m.z*m.z + m.w*m.w;
}
__device__ __forceinline__ float fullred(float v) {
    #pragma unroll
    for (int o = 16; o; o >>= 1) v += __shfl_xor_sync(FULLM, v, o);
    return v;
}

__global__ void __launch_bounds__(TPB, 1) k_all(
    const float* __restrict__ x, const float* __restrict__ W,
    const float* __restrict__ bvec, const float* __restrict__ mem,
    float* __restrict__ out)
{
    extern __shared__ __align__(16) char smraw[];
    float* sBuf  = (float*)(smraw + OFF_BUF);    // [NBUF][128][128]
    float* sE    = (float*)(smraw + OFF_E);      // [NBUF][136]
    float* sRed  = (float*)(smraw + OFF_RED);    // [16][128]
    float* sF    = (float*)(smraw + OFF_F);      // [144]
    float* sP    = (float*)(smraw + OFF_P);      // [12]
    float* sZw   = (float*)(smraw + OFF_ZW);     // [16]
    uint64_t* sMb = (uint64_t*)(smraw + OFF_MBAR);
    int* sLast   = (int*)(smraw + OFF_LAST);

    const int tid = threadIdx.x, warp = tid >> 5, lane = tid & 31;
    const int bid = blockIdx.x;

    const int ts = (int)(((long long)bid * NTILES) / MB);
    const int te = (int)(((long long)(bid + 1) * NTILES) / MB);

    // ---------------- mbarrier init + TMA prologue (overlaps factor stage) ----------------
    const uint32_t mb0 = smem_u32(&sMb[0]);
    if (tid == 0) {
        #pragma unroll
        for (int i = 0; i < NBUF; i++) mbar_init(mb0 + 8u * i, 1);
        asm volatile("fence.proxy.async.shared::cta;" ::: "memory");
    }
    __syncthreads();
    if (tid == 0) {
        #pragma unroll
        for (int i = 0; i < NBUF; i++) {
            if (ts + i < te) {
                mbar_expect_tx(mb0 + 8u * i, BUF_BYTES);
                tma_bulk_g2s(smem_u32(sBuf + i * TILE * DIM),
                             mem + (size_t)(ts + i) * TILE * DIM, BUF_BYTES, mb0 + 8u * i);
            }
        }
    }

    // ---------------- stage 1: factor partials (blocks 0..FB-1) ----------------
    if (bid < FB) {
        const int kb = bid / 5, fb = bid % 5;
        const int f = fb * 32 + lane;
        float a = 0.f;
        if (f < NF) {
            const int k0 = kb * 64 + warp * 4;
            #pragma unroll
            for (int i = 0; i < 4; i++)
                a += __ldg(&x[k0 + i]) * __ldg(&W[(size_t)(k0 + i) * NF + f]);
        }
        sRed[warp * 32 + lane] = a;
        __syncthreads();
        if (warp == 0) {
            float s = a;
            #pragma unroll
            for (int w = 1; w < NWARPS; w++) s += sRed[w * 32 + lane];
            g_fpart[kb][fb * 32 + lane] = s;
        }
        __threadfence();
        __syncthreads();
        if (tid == 0) atomicAdd(&g_cnt1, 1);
    }

    // ---------------- grid sync on factor partials ----------------
    if (tid == 0) {
        int v;
        do {
            asm volatile("ld.global.acquire.gpu.b32 %0, [%1];" : "=r"(v) : "l"(&g_cnt1));
            if (v < FB) __nanosleep(128);
        } while (v < FB);
    }
    __syncthreads();

    // ---------------- per-block prep ----------------
    if (tid < 160) {
        float s = 0.f;
        #pragma unroll
        for (int p = 0; p < KCH; p++) s += g_fpart[p][tid];
        if (tid < 144) sF[tid] = (tid < NF) ? s + __ldg(&bvec[tid]) : 0.f;
    }
    __syncthreads();
    if (warp < 4) {
        const float v = sF[warp * 32 + lane];
        float sq = fullred(v * v);
        if (lane == 0) sZw[warp] = sq;
    }
    __syncthreads();
    if (tid == 0) {
        const float tot = sZw[0] + sZw[1] + sZw[2] + sZw[3];
        const float ks = sF[DIM];
        sP[0] = ks;
        sP[1] = fabsf(ks);                     // stabilizer (constant cancels in normalization)
        sP[2] = 1.f / fmaxf(sqrtf(tot), 1e-8f);
        sP[3] = fmaxf(sF[NF - 1], 0.f) + 1.f;  // sharpening
        float mx = -1e30f;
        #pragma unroll
        for (int j = 0; j < 7; j++) mx = fmaxf(mx, sF[DIM + 2 + j]);
        float ssum = 0.f, ev[7];
        #pragma unroll
        for (int j = 0; j < 7; j++) { ev[j] = expf(sF[DIM + 2 + j] - mx); ssum += ev[j]; }
        #pragma unroll
        for (int j = 0; j < 7; j++) sP[4 + j] = ev[j] / ssum;
        // gate = softmax(single element) == 1.0 exactly -> previous_weighting unused
    }
    __syncthreads();

    const float4 kv = ((const float4*)sF)[lane];
    const float ks = sP[0], stab = sP[1], ikn = sP[2], sharp = sP[3];
    float sh[7];
    #pragma unroll
    for (int j = 0; j < 7; j++) sh[j] = sP[4 + j];

    // ---- left window: rows ts*128-3..+2 -> sE[0][0..5] (one-time LDG) ----
    if (warp < 6) {
        int g = ts * TILE - HALO + warp;
        if (g < 0) g += N_SLOTS;
        const float4 v = ((const float4*)(mem + (size_t)g * DIM))[lane];
        float d, q; rowstat(v, kv, d, q);
        d = fullred(d); q = fullred(q);
        if (lane == 0)
            sE[warp] = __expf(ks * (d * ikn * rsqrtf(fmaxf(q, 1e-16f))) - stab);
    }

    const int r0 = warp * RPW;
    const bool hw = (warp >= NWARPS - 3);
    const int hoff = warp - (NWARPS - 3);

    float4 acc = make_float4(0.f, 0.f, 0.f, 0.f);
    float zacc = 0.f;

    for (int t = ts, c = 0; t < te; ++t, ++c) {
        const int ci = c % NBUF;
        const int ni = (c + 1) % NBUF;
        float* Ecur = sE + ci * 136;
        float* Enxt = sE + ni * 136;
        const float* buf = sBuf + ci * TILE * DIM;

        // wait this tile's TMA
        mbar_wait(mb0 + 8u * ci, (c / NBUF) & 1);

        // load owned rows from smem into regs
        float4 m[RPW];
        #pragma unroll
        for (int i = 0; i < RPW; i++)
            m[i] = ((const float4*)(buf + (size_t)(r0 + i) * DIM))[lane];

        // ---- butterfly e for owned rows (2 groups of 4) ----
        #pragma unroll
        for (int i0 = 0; i0 < RPW; i0 += 4) {
            float d[4], q[4];
            #pragma unroll
            for (int u = 0; u < 4; u++) rowstat(m[i0 + u], kv, d[u], q[u]);
            #pragma unroll
            for (int u = 0; u < 4; u++) {
                d[u] += __shfl_xor_sync(FULLM, d[u], 1);
                q[u] += __shfl_xor_sync(FULLM, q[u], 1);
            }
            float a0 = (lane & 1) ? q[0] : d[0];
            float a1 = (lane & 1) ? q[1] : d[1];
            float a2 = (lane & 1) ? q[2] : d[2];
            float a3 = (lane & 1) ? q[3] : d[3];
            a0 += __shfl_xor_sync(FULLM, a0, 2);
            a1 += __shfl_xor_sync(FULLM, a1, 2);
            a2 += __shfl_xor_sync(FULLM, a2, 2);
            a3 += __shfl_xor_sync(FULLM, a3, 2);
            float b0 = (lane & 2) ? a2 : a0;
            float b1 = (lane & 2) ? a3 : a1;
            b0 += __shfl_xor_sync(FULLM, b0, 4);
            b1 += __shfl_xor_sync(FULLM, b1, 4);
            float cc = (lane & 4) ? b1 : b0;
            cc += __shfl_xor_sync(FULLM, cc, 8);
            cc += __shfl_xor_sync(FULLM, cc, 16);
            const float qq = __shfl_xor_sync(FULLM, cc, 1);
            if (lane < 8 && !(lane & 1)) {
                const int row = ((lane & 2) ? 2 : 0) + ((lane & 4) ? 1 : 0);
                const int p = 3 + r0 + i0 + row;
                if (p >= 6) {
                    const float e = __expf(ks * (cc * ikn * rsqrtf(fmaxf(qq, 1e-16f))) - stab);
                    Ecur[p] = e;
                    if (p >= 128) Enxt[p - 128] = e;   // carry
                }
            }
        }

        // ---- right halo: rows 0..2 of tile t+1 (from next ring buffer; LDG at range end) ----
        if (hw) {
            float4 v;
            if (t + 1 < te) {
                mbar_wait(mb0 + 8u * ni, ((c + 1) / NBUF) & 1);
                v = ((const float4*)(sBuf + ni * TILE * DIM + (size_t)hoff * DIM))[lane];
            } else {
                int g = te * TILE + hoff;
                if (g >= N_SLOTS) g -= N_SLOTS;
                v = ((const float4*)(mem + (size_t)g * DIM))[lane];
            }
            float d, q; rowstat(v, kv, d, q);
            d = fullred(d); q = fullred(q);
            if (lane == 0) {
                const float e = __expf(ks * (d * ikn * rsqrtf(fmaxf(q, 1e-16f))) - stab);
                Ecur[131 + hoff] = e;
                Enxt[3 + hoff]   = e;
            }
        }
        __syncthreads();   // window complete; also fences all reads of buf ci

        // ---- pw: lanes 0..7, one owned row each ----
        float pw = 0.f;
        if (lane < RPW) {
            const int p0 = r0 + lane;
            float tc = 0.f;
            #pragma unroll
            for (int j = 0; j < 7; j++) tc += sh[j] * Ecur[p0 + j];
            pw = __powf(tc, sharp);   // tc > 0 always
            zacc += pw;
        }
        // ---- accumulate from registers ----
        #pragma unroll
        for (int r = 0; r < RPW; r++) {
            const float pwb = __shfl_sync(FULLM, pw, r);
            acc.x += pwb * m[r].x; acc.y += pwb * m[r].y;
            acc.z += pwb * m[r].z; acc.w += pwb * m[r].w;
        }

        // ---- refill this buffer with tile t+NBUF ----
        if (tid == 0 && t + NBUF < te) {
            mbar_expect_tx(mb0 + 8u * ci, BUF_BYTES);
            tma_bulk_g2s(smem_u32(sBuf + ci * TILE * DIM),
                         mem + (size_t)(t + NBUF) * TILE * DIM, BUF_BYTES, mb0 + 8u * ci);
        }
    }

    // ---------------- deterministic block reduction + transposed store ----------------
    __syncthreads();
    ((float4*)(sRed + warp * DIM))[lane] = acc;
    zacc = fullred(zacc);
    if (lane == 0) sZw[warp] = zacc;
    __syncthreads();
    if (tid < DIM) {
        float u = 0.f;
        #pragma unroll
        for (int w = 0; w < NWARPS; w++) u += sRed[w * DIM + tid];
        g_UpartT[tid][bid] = u;
    }
    if (tid == 0) {
        float z = 0.f;
        #pragma unroll
        for (int w = 0; w < NWARPS; w++) z += sZw[w];
        g_Zpart[bid] = z;
    }
    __threadfence();
    __syncthreads();

    // ---------------- fused finisher: last-done block reduces in FIXED order ----------------
    if (tid == 0) *sLast = (atomicAdd(&g_cnt2, 1) == MB - 1) ? 1 : 0;
    __syncthreads();
    if (*sLast) {
        __threadfence();
        float z = 0.f;
        for (int i = lane; i < MB; i += 32) z += g_Zpart[i];
        z = fullred(z);
        for (int d = warp; d < DIM; d += NWARPS) {
            float u = 0.f;
            for (int i = lane; i < MB; i += 32) u += g_UpartT[d][i];
            u = fullred(u);
            if (lane == 0) out[d] = u / z;
        }
        if (tid == 0) { g_cnt1 = 0; g_cnt2 = 0; __threadfence(); }  // reset for next replay
    }
}

extern "C" void kernel_launch(void* const* d_in, const int* in_sizes, int n_in,
                              void* d_out, int out_size) {
    // Bind inputs by UNIQUE element count (robust to metadata ordering):
    // x=1024, prev=524288 (unused: gate==1), mem=67108864, W=141312, b=138
    const float *x = 0, *mem = 0, *W = 0, *b = 0;
    for (int i = 0; i < n_in; i++) {
        switch (in_sizes[i]) {
            case DIN:            x   = (const float*)d_in[i]; break;
            case N_SLOTS * DIM:  mem = (const float*)d_in[i]; break;
            case DIN * NF:       W   = (const float*)d_in[i]; break;
            case NF:             b   = (const float*)d_in[i]; break;
            default: break;      // previous_weighting (N_SLOTS): unused
        }
    }
    float* out = (float*)d_out;

    cudaFuncSetAttribute(k_all, cudaFuncAttributeMaxDynamicSharedMemorySize, SMEM_TOTAL);
    k_all<<<MB, TPB, SMEM_TOTAL>>>(x, W, b, mem, out);
}